// round 8
// baseline (speedup 1.0000x reference)
#include <cuda_runtime.h>
#include <mma.h>
#include <math.h>
#include <stdint.h>

using namespace nvcuda;

#define NUM_E 8
#define BATCH 4096
#define DIM   1024
#define DHID  4096

// --- device scratch (no allocations allowed) ---
__device__ int   g_cnt[NUM_E];
__device__ int   g_cur[NUM_E];
__device__ int   g_off[NUM_E + 1];
__device__ int   g_perm[BATCH];
__device__ float g_hid[(size_t)BATCH * DHID];          // 64 MB, permuted, tf32-rounded
__device__ float g_w1c[(size_t)NUM_E * DIM * DHID];    // 128 MB tf32-rounded W1
__device__ float g_w2c[(size_t)NUM_E * DHID * DIM];    // 128 MB tf32-rounded W2
__device__ float g_yc[(size_t)BATCH * DIM];            // 16 MB tf32-rounded y

// ---------------- helpers ----------------
__device__ __forceinline__ float to_tf32(float x) {
    float r;
    asm("cvt.rna.tf32.f32 %0, %1;" : "=f"(r) : "f"(x));
    return r;
}
__device__ __forceinline__ float sigmoidf_(float x) { return 1.0f / (1.0f + expf(-x)); }

__device__ __forceinline__ void cp16(uint32_t dst, const float* src) {
    asm volatile("cp.async.cg.shared.global [%0], [%1], 16;\n" :: "r"(dst), "l"(src));
}
__device__ __forceinline__ void cp_commit() { asm volatile("cp.async.commit_group;\n" ::); }
__device__ __forceinline__ void cp_wait0()  { asm volatile("cp.async.wait_group 0;\n" ::); }

// ---------------- routing ----------------
__global__ void k_zero() {
    int i = threadIdx.x;
    if (i < NUM_E) { g_cnt[i] = 0; g_cur[i] = 0; }
}

__device__ __forceinline__ int expert_of(float t) {
    int e = (int)(t * 8.0f);
    if (e < 0) e = 0;
    if (e > NUM_E - 1) e = NUM_E - 1;
    return e;
}

__global__ void k_hist(const float* __restrict__ t) {
    int i = blockIdx.x * blockDim.x + threadIdx.x;
    if (i < BATCH) atomicAdd(&g_cnt[expert_of(t[i])], 1);
}

__global__ void k_scan() {
    if (threadIdx.x == 0) {
        int s = 0;
        for (int e = 0; e < NUM_E; e++) { g_off[e] = s; s += g_cnt[e]; }
        g_off[NUM_E] = s;
    }
}

__global__ void k_scatter(const float* __restrict__ t) {
    int i = blockIdx.x * blockDim.x + threadIdx.x;
    if (i < BATCH) {
        int e = expert_of(t[i]);
        int p = atomicAdd(&g_cur[e], 1);
        g_perm[g_off[e] + p] = i;
    }
}

// ---------------- tf32 pre-conversion (elementwise, float4) ----------------
__global__ void k_cvt(const float* __restrict__ src, float* __restrict__ dst, int n4) {
    int i = blockIdx.x * blockDim.x + threadIdx.x;
    int stride = gridDim.x * blockDim.x;
    for (; i < n4; i += stride) {
        float4 v = ((const float4*)src)[i];
        v.x = to_tf32(v.x); v.y = to_tf32(v.y);
        v.z = to_tf32(v.z); v.w = to_tf32(v.w);
        ((float4*)dst)[i] = v;
    }
}

// ---------------- tf32 WMMA GEMMs: 128x128x32, cp.async double-buffered ----------------
#define AS_STRIDE 40
#define BS_STRIDE 136
#define ASZ (128 * AS_STRIDE)   // floats per A stage
#define BSZ (32  * BS_STRIDE)   // floats per B stage
#define STAGE_SZ (ASZ + BSZ)
#define SMEM_FLOATS (2 * STAGE_SZ + 8 * 256)
#define SMEM_BYTES  (SMEM_FLOATS * 4)

typedef wmma::fragment<wmma::matrix_a, 16, 16, 8, wmma::precision::tf32, wmma::row_major> FragA;
typedef wmma::fragment<wmma::matrix_b, 16, 16, 8, wmma::precision::tf32, wmma::row_major> FragB;
typedef wmma::fragment<wmma::accumulator, 16, 16, 8, float> FragC;

// GEMM1: hid[seg0+m][n] = tf32(tanh( yc[perm[seg0+m]] . W1c[e][:,n] + b1[e][n] ))
__global__ __launch_bounds__(256, 2)
void k_gemm1(const float* __restrict__ b1)
{
    const int e    = blockIdx.z;
    const int seg0 = g_off[e];
    const int cnt  = g_off[e + 1] - seg0;
    const int tm   = blockIdx.y;
    if (tm * 128 >= cnt) return;
    const int tn = blockIdx.x;

    extern __shared__ float smem[];
    float* As[2] = { smem,            smem + STAGE_SZ };
    float* Bs[2] = { smem + ASZ,      smem + STAGE_SZ + ASZ };
    float* Cs    = smem + 2 * STAGE_SZ;

    const int tid  = threadIdx.x;
    const int wid  = tid >> 5;
    const int lane = tid & 31;
    const int wm   = wid >> 2;   // 0..1
    const int wn   = wid & 3;    // 0..3

    // A loader: 4 float4 slots/thread over 128x32
    const float* asrc[4];
    uint32_t adst[2][4];
    int arow_[4];
#pragma unroll
    for (int i = 0; i < 4; i++) {
        int lin = tid + i * 256;
        int arow = lin >> 3;
        int ak4  = (lin & 7) * 4;
        arow_[i] = arow;
        int gm = tm * 128 + arow;
        int sr = (gm < cnt) ? g_perm[seg0 + gm] : g_perm[seg0];  // clamp: garbage rows never stored
        asrc[i] = g_yc + (size_t)sr * DIM + ak4;
        adst[0][i] = (uint32_t)__cvta_generic_to_shared(&As[0][arow * AS_STRIDE + ak4]);
        adst[1][i] = (uint32_t)__cvta_generic_to_shared(&As[1][arow * AS_STRIDE + ak4]);
    }
    // B loader: 4 float4 slots/thread over 32x128
    const float* bsrc[4];
    uint32_t bdst[2][4];
    const float* Wbase = g_w1c + (size_t)e * DIM * DHID + (size_t)tn * 128;
#pragma unroll
    for (int i = 0; i < 4; i++) {
        int lin = tid + i * 256;
        int bk  = lin >> 5;
        int bn4 = (lin & 31) * 4;
        bsrc[i] = Wbase + (size_t)bk * DHID + bn4;
        bdst[0][i] = (uint32_t)__cvta_generic_to_shared(&Bs[0][bk * BS_STRIDE + bn4]);
        bdst[1][i] = (uint32_t)__cvta_generic_to_shared(&Bs[1][bk * BS_STRIDE + bn4]);
    }

    FragC acc[4][2];
#pragma unroll
    for (int i = 0; i < 4; i++)
#pragma unroll
        for (int j = 0; j < 2; j++) wmma::fill_fragment(acc[i][j], 0.0f);

    const int nstage = DIM / 32;
    // prologue: stage 0 -> buf 0
#pragma unroll
    for (int i = 0; i < 4; i++) cp16(adst[0][i], asrc[i]);
#pragma unroll
    for (int i = 0; i < 4; i++) cp16(bdst[0][i], bsrc[i]);
    cp_commit();

    int p = 0;
    for (int kt = 0; kt < nstage; kt++) {
        cp_wait0();
        __syncthreads();
        if (kt + 1 < nstage) {
            const int k0 = (kt + 1) * 32;
#pragma unroll
            for (int i = 0; i < 4; i++) cp16(adst[p ^ 1][i], asrc[i] + k0);
#pragma unroll
            for (int i = 0; i < 4; i++) cp16(bdst[p ^ 1][i], bsrc[i] + (size_t)k0 * DHID);
            cp_commit();
        }
        const float* a_s = As[p];
        const float* b_s = Bs[p];
#pragma unroll
        for (int kk = 0; kk < 4; kk++) {
            FragA a[4];
            FragB b[2];
#pragma unroll
            for (int fm = 0; fm < 4; fm++)
                wmma::load_matrix_sync(a[fm], &a_s[(wm * 64 + fm * 16) * AS_STRIDE + kk * 8], AS_STRIDE);
#pragma unroll
            for (int fn = 0; fn < 2; fn++)
                wmma::load_matrix_sync(b[fn], &b_s[(kk * 8) * BS_STRIDE + wn * 32 + fn * 16], BS_STRIDE);
#pragma unroll
            for (int fm = 0; fm < 4; fm++)
#pragma unroll
                for (int fn = 0; fn < 2; fn++)
                    wmma::mma_sync(acc[fm][fn], a[fm], b[fn], acc[fm][fn]);
        }
        p ^= 1;
    }
    __syncthreads();

    // epilogue: tf32(tanh(acc + b1)) -> g_hid (permuted rows, contiguous)
    float* cbuf = &Cs[wid * 256];
    const float* b1e = b1 + (size_t)e * DHID;
#pragma unroll
    for (int fm = 0; fm < 4; fm++) {
#pragma unroll
        for (int fn = 0; fn < 2; fn++) {
            wmma::store_matrix_sync(cbuf, acc[fm][fn], 16, wmma::mem_row_major);
            __syncwarp();
#pragma unroll
            for (int j = 0; j < 8; j++) {
                int idx = lane + j * 32;
                int r = idx >> 4, c = idx & 15;
                int gm   = tm * 128 + wm * 64 + fm * 16 + r;
                int gcol = tn * 128 + wn * 32 + fn * 16 + c;
                if (gm < cnt)
                    g_hid[(size_t)(seg0 + gm) * DHID + gcol] = to_tf32(tanhf(cbuf[idx] + b1e[gcol]));
            }
            __syncwarp();
        }
    }
}

// GEMM2 + epilogue: out[perm[m]] = cf*sig(scales)*(hid.W2 + b2) + cy*y[perm[m]]
__global__ __launch_bounds__(256, 2)
void k_gemm2(const float* __restrict__ y, const float* __restrict__ b2,
             const float* __restrict__ scales, const float* __restrict__ shifta,
             const float* __restrict__ shiftb, float* __restrict__ out)
{
    const int e    = blockIdx.z;
    const int seg0 = g_off[e];
    const int cnt  = g_off[e + 1] - seg0;
    const int tm   = blockIdx.y;
    if (tm * 128 >= cnt) return;
    const int tn = blockIdx.x;

    extern __shared__ float smem[];
    float* As[2] = { smem,            smem + STAGE_SZ };
    float* Bs[2] = { smem + ASZ,      smem + STAGE_SZ + ASZ };
    float* Cs    = smem + 2 * STAGE_SZ;

    const int tid  = threadIdx.x;
    const int wid  = tid >> 5;
    const int lane = tid & 31;
    const int wm   = wid >> 2;
    const int wn   = wid & 3;

    const float* asrc[4];
    uint32_t adst[2][4];
#pragma unroll
    for (int i = 0; i < 4; i++) {
        int lin = tid + i * 256;
        int arow = lin >> 3;
        int ak4  = (lin & 7) * 4;
        int gm = tm * 128 + arow;
        int rr = (gm < cnt) ? gm : 0;            // clamp inside segment
        asrc[i] = g_hid + (size_t)(seg0 + rr) * DHID + ak4;
        adst[0][i] = (uint32_t)__cvta_generic_to_shared(&As[0][arow * AS_STRIDE + ak4]);
        adst[1][i] = (uint32_t)__cvta_generic_to_shared(&As[1][arow * AS_STRIDE + ak4]);
    }
    const float* bsrc[4];
    uint32_t bdst[2][4];
    const float* Wbase = g_w2c + (size_t)e * DHID * DIM + (size_t)tn * 128;
#pragma unroll
    for (int i = 0; i < 4; i++) {
        int lin = tid + i * 256;
        int bk  = lin >> 5;
        int bn4 = (lin & 31) * 4;
        bsrc[i] = Wbase + (size_t)bk * DIM + bn4;
        bdst[0][i] = (uint32_t)__cvta_generic_to_shared(&Bs[0][bk * BS_STRIDE + bn4]);
        bdst[1][i] = (uint32_t)__cvta_generic_to_shared(&Bs[1][bk * BS_STRIDE + bn4]);
    }

    FragC acc[4][2];
#pragma unroll
    for (int i = 0; i < 4; i++)
#pragma unroll
        for (int j = 0; j < 2; j++) wmma::fill_fragment(acc[i][j], 0.0f);

    const int nstage = DHID / 32;
#pragma unroll
    for (int i = 0; i < 4; i++) cp16(adst[0][i], asrc[i]);
#pragma unroll
    for (int i = 0; i < 4; i++) cp16(bdst[0][i], bsrc[i]);
    cp_commit();

    int p = 0;
    for (int kt = 0; kt < nstage; kt++) {
        cp_wait0();
        __syncthreads();
        if (kt + 1 < nstage) {
            const int k0 = (kt + 1) * 32;
#pragma unroll
            for (int i = 0; i < 4; i++) cp16(adst[p ^ 1][i], asrc[i] + k0);
#pragma unroll
            for (int i = 0; i < 4; i++) cp16(bdst[p ^ 1][i], bsrc[i] + (size_t)k0 * DIM);
            cp_commit();
        }
        const float* a_s = As[p];
        const float* b_s = Bs[p];
#pragma unroll
        for (int kk = 0; kk < 4; kk++) {
            FragA a[4];
            FragB b[2];
#pragma unroll
            for (int fm = 0; fm < 4; fm++)
                wmma::load_matrix_sync(a[fm], &a_s[(wm * 64 + fm * 16) * AS_STRIDE + kk * 8], AS_STRIDE);
#pragma unroll
            for (int fn = 0; fn < 2; fn++)
                wmma::load_matrix_sync(b[fn], &b_s[(kk * 8) * BS_STRIDE + wn * 32 + fn * 16], BS_STRIDE);
#pragma unroll
            for (int fm = 0; fm < 4; fm++)
#pragma unroll
                for (int fn = 0; fn < 2; fn++)
                    wmma::mma_sync(acc[fm][fn], a[fm], b[fn], acc[fm][fn]);
        }
        p ^= 1;
    }
    __syncthreads();

    const float s_a = sigmoidf_(shifta[0]);
    const float s_b = sigmoidf_(shiftb[0]);
    const float cf  = 0.5f * (s_a + s_b);
    const float cy  = 0.5f * (s_b - s_a);

    float* cbuf = &Cs[wid * 256];
    const float* b2e = b2 + (size_t)e * DIM;
#pragma unroll
    for (int fm = 0; fm < 4; fm++) {
#pragma unroll
        for (int fn = 0; fn < 2; fn++) {
            wmma::store_matrix_sync(cbuf, acc[fm][fn], 16, wmma::mem_row_major);
            __syncwarp();
#pragma unroll
            for (int j = 0; j < 8; j++) {
                int idx = lane + j * 32;
                int r = idx >> 4, c = idx & 15;
                int gm   = tm * 128 + wm * 64 + fm * 16 + r;
                int gcol = tn * 128 + wn * 32 + fn * 16 + c;
                if (gm < cnt) {
                    int orow = g_perm[seg0 + gm];
                    float f = cbuf[idx] + b2e[gcol];
                    f = sigmoidf_(scales[gcol]) * f;
                    out[(size_t)orow * DIM + gcol] = cf * f + cy * y[(size_t)orow * DIM + gcol];
                }
            }
            __syncwarp();
        }
    }
}

// ---------------- launch ----------------
extern "C" void kernel_launch(void* const* d_in, const int* in_sizes, int n_in,
                              void* d_out, int out_size)
{
    const float* t      = (const float*)d_in[0];
    const float* y      = (const float*)d_in[1];
    const float* W1     = (const float*)d_in[2];
    const float* b1     = (const float*)d_in[3];
    const float* W2     = (const float*)d_in[4];
    const float* b2     = (const float*)d_in[5];
    const float* scales = (const float*)d_in[6];
    const float* shifta = (const float*)d_in[7];
    const float* shiftb = (const float*)d_in[8];
    float* out = (float*)d_out;

    static int smem_set = 0;
    if (!smem_set) {
        cudaFuncSetAttribute(k_gemm1, cudaFuncAttributeMaxDynamicSharedMemorySize, SMEM_BYTES);
        cudaFuncSetAttribute(k_gemm2, cudaFuncAttributeMaxDynamicSharedMemorySize, SMEM_BYTES);
        smem_set = 1;
    }

    k_zero<<<1, 32>>>();
    k_hist<<<(BATCH + 255) / 256, 256>>>(t);
    k_scan<<<1, 1>>>();
    k_scatter<<<(BATCH + 255) / 256, 256>>>(t);

    // tf32 pre-rounding passes
    float* w1c; cudaGetSymbolAddress((void**)&w1c, g_w1c);
    float* w2c; cudaGetSymbolAddress((void**)&w2c, g_w2c);
    float* yc;  cudaGetSymbolAddress((void**)&yc,  g_yc);
    k_cvt<<<4096, 256>>>(y,  yc,  (BATCH * DIM) / 4);
    k_cvt<<<4096, 256>>>(W1, w1c, (NUM_E * DIM * DHID) / 4);
    k_cvt<<<4096, 256>>>(W2, w2c, (NUM_E * DHID * DIM) / 4);

    dim3 g1(DHID / 128, BATCH / 128, NUM_E);
    k_gemm1<<<g1, 256, SMEM_BYTES>>>(b1);

    dim3 g2(DIM / 128, BATCH / 128, NUM_E);
    k_gemm2<<<g2, 256, SMEM_BYTES>>>(y, b2, scales, shifta, shiftb, out);
}

// round 12
// speedup vs baseline: 3.0079x; 3.0079x over previous
#include <cuda_runtime.h>
#include <cuda_fp16.h>
#include <mma.h>
#include <math.h>
#include <stdint.h>

using namespace nvcuda;

#define NUM_E 8
#define BATCH 4096
#define DIM   1024
#define DHID  4096

// --- device scratch (no allocations allowed) ---
__device__ int    g_cnt[NUM_E];
__device__ int    g_cur[NUM_E];
__device__ int    g_off[NUM_E + 1];
__device__ int    g_perm[BATCH];
__device__ __half g_hid[(size_t)BATCH * DHID];   // 32 MB, permuted rows, fp16

// ---------------- routing ----------------
__global__ void k_zero() {
    int i = threadIdx.x;
    if (i < NUM_E) { g_cnt[i] = 0; g_cur[i] = 0; }
}

__device__ __forceinline__ int expert_of(float t) {
    int e = (int)(t * 8.0f);
    if (e < 0) e = 0;
    if (e > NUM_E - 1) e = NUM_E - 1;
    return e;
}

__global__ void k_hist(const float* __restrict__ t) {
    int i = blockIdx.x * blockDim.x + threadIdx.x;
    if (i < BATCH) atomicAdd(&g_cnt[expert_of(t[i])], 1);
}

__global__ void k_scan() {
    if (threadIdx.x == 0) {
        int s = 0;
        for (int e = 0; e < NUM_E; e++) { g_off[e] = s; s += g_cnt[e]; }
        g_off[NUM_E] = s;
    }
}

__global__ void k_scatter(const float* __restrict__ t) {
    int i = blockIdx.x * blockDim.x + threadIdx.x;
    if (i < BATCH) {
        int e = expert_of(t[i]);
        int p = atomicAdd(&g_cur[e], 1);
        g_perm[g_off[e] + p] = i;
    }
}

__device__ __forceinline__ float sigmoidf_(float x) { return 1.0f / (1.0f + expf(-x)); }

__device__ __forceinline__ uint4 f8_to_h8(float4 a, float4 b) {
    __half2 h0 = __floats2half2_rn(a.x, a.y);
    __half2 h1 = __floats2half2_rn(a.z, a.w);
    __half2 h2 = __floats2half2_rn(b.x, b.y);
    __half2 h3 = __floats2half2_rn(b.z, b.w);
    uint4 r;
    r.x = *(uint32_t*)&h0; r.y = *(uint32_t*)&h1;
    r.z = *(uint32_t*)&h2; r.w = *(uint32_t*)&h3;
    return r;
}

// ---------------- fp16 WMMA tiles: 128x128x32, 8 warps, warp = 64x32 ----------------
#define AS_STRIDE 40     // halves (80B rows, 16B-aligned)
#define BS_STRIDE 136    // halves (272B rows, 16B-aligned)

typedef wmma::fragment<wmma::matrix_a, 16, 16, 16, __half, wmma::row_major> FragA;
typedef wmma::fragment<wmma::matrix_b, 16, 16, 16, __half, wmma::row_major> FragB;
typedef wmma::fragment<wmma::accumulator, 16, 16, 16, float> FragC;

// GEMM1: g_hid[seg0+m][n] = half( tanh( y[perm[seg0+m]] . W1[e][:,n] + b1[e][n] ) )
__global__ __launch_bounds__(256)
void k_gemm1(const float* __restrict__ y, const float* __restrict__ W1,
             const float* __restrict__ b1)
{
    const int e    = blockIdx.z;
    const int seg0 = g_off[e];
    const int cnt  = g_off[e + 1] - seg0;
    const int tm   = blockIdx.y;
    if (tm * 128 >= cnt) return;
    const int tn = blockIdx.x;

    __shared__ __half As[128 * AS_STRIDE];   // 10 KB
    __shared__ __half Bs[32 * BS_STRIDE];    // 8.5 KB
    __shared__ float  Cs[8 * 256];           // 8 KB

    const int tid  = threadIdx.x;
    const int wid  = tid >> 5;
    const int lane = tid & 31;
    const int wm   = wid >> 2;   // 0..1
    const int wn   = wid & 3;    // 0..3

    // A loader: 2 slots/thread, slot = 8 halves along k. 128 rows x 4 slots.
    const float* asrc[2];
    int arow[2], ak8[2];
#pragma unroll
    for (int i = 0; i < 2; i++) {
        int lin = tid + i * 256;           // 0..511
        arow[i] = lin >> 2;
        ak8[i]  = (lin & 3) * 8;
        int gm  = tm * 128 + arow[i];
        int sr  = (gm < cnt) ? g_perm[seg0 + gm] : g_perm[seg0];
        asrc[i] = y + (size_t)sr * DIM + ak8[i];
    }
    // B loader: 2 slots/thread over 32 k-rows x 16 slots (8 halves along n)
    const float* bsrc[2];
    int bk[2], bn8[2];
    const float* Wbase = W1 + (size_t)e * DIM * DHID + (size_t)tn * 128;
#pragma unroll
    for (int i = 0; i < 2; i++) {
        int lin = tid + i * 256;
        bk[i]  = lin >> 4;
        bn8[i] = (lin & 15) * 8;
        bsrc[i] = Wbase + (size_t)bk[i] * DHID + bn8[i];
    }

    FragC acc[4][2];
#pragma unroll
    for (int i = 0; i < 4; i++)
#pragma unroll
        for (int j = 0; j < 2; j++) wmma::fill_fragment(acc[i][j], 0.0f);

    // prefetch stage 0
    float4 pa[2][2], pb[2][2];
#pragma unroll
    for (int i = 0; i < 2; i++) {
        pa[i][0] = *(const float4*)(asrc[i]);
        pa[i][1] = *(const float4*)(asrc[i] + 4);
        pb[i][0] = *(const float4*)(bsrc[i]);
        pb[i][1] = *(const float4*)(bsrc[i] + 4);
    }

    const int nstage = DIM / 32;
    for (int kt = 0; kt < nstage; kt++) {
#pragma unroll
        for (int i = 0; i < 2; i++) {
            *(uint4*)&As[arow[i] * AS_STRIDE + ak8[i]] = f8_to_h8(pa[i][0], pa[i][1]);
            *(uint4*)&Bs[bk[i] * BS_STRIDE + bn8[i]]   = f8_to_h8(pb[i][0], pb[i][1]);
        }
        __syncthreads();

        if (kt + 1 < nstage) {
            const int k0 = (kt + 1) * 32;
#pragma unroll
            for (int i = 0; i < 2; i++) {
                pa[i][0] = *(const float4*)(asrc[i] + k0);
                pa[i][1] = *(const float4*)(asrc[i] + k0 + 4);
                pb[i][0] = *(const float4*)(bsrc[i] + (size_t)k0 * DHID);
                pb[i][1] = *(const float4*)(bsrc[i] + (size_t)k0 * DHID + 4);
            }
        }

#pragma unroll
        for (int kk = 0; kk < 2; kk++) {
            FragA a[4];
            FragB b[2];
#pragma unroll
            for (int fm = 0; fm < 4; fm++)
                wmma::load_matrix_sync(a[fm], &As[(wm * 64 + fm * 16) * AS_STRIDE + kk * 16], AS_STRIDE);
#pragma unroll
            for (int fn = 0; fn < 2; fn++)
                wmma::load_matrix_sync(b[fn], &Bs[(kk * 16) * BS_STRIDE + wn * 32 + fn * 16], BS_STRIDE);
#pragma unroll
            for (int fm = 0; fm < 4; fm++)
#pragma unroll
                for (int fn = 0; fn < 2; fn++)
                    wmma::mma_sync(acc[fm][fn], a[fm], b[fn], acc[fm][fn]);
        }
        __syncthreads();
    }

    // epilogue: tanh(acc + b1) -> g_hid (half, permuted rows)
    float* cbuf = &Cs[wid * 256];
    const float* b1e = b1 + (size_t)e * DHID;
#pragma unroll
    for (int fm = 0; fm < 4; fm++) {
#pragma unroll
        for (int fn = 0; fn < 2; fn++) {
            wmma::store_matrix_sync(cbuf, acc[fm][fn], 16, wmma::mem_row_major);
            __syncwarp();
#pragma unroll
            for (int j = 0; j < 8; j++) {
                int idx = lane + j * 32;
                int r = idx >> 4, c = idx & 15;
                int gm   = tm * 128 + wm * 64 + fm * 16 + r;
                int gcol = tn * 128 + wn * 32 + fn * 16 + c;
                if (gm < cnt)
                    g_hid[(size_t)(seg0 + gm) * DHID + gcol] =
                        __float2half_rn(tanhf(cbuf[idx] + b1e[gcol]));
            }
            __syncwarp();
        }
    }
}

// GEMM2 + epilogue: out[perm[m]] = cf*sig(scales)*(hid.W2 + b2) + cy*y[perm[m]]
__global__ __launch_bounds__(256)
void k_gemm2(const float* __restrict__ y, const float* __restrict__ W2,
             const float* __restrict__ b2, const float* __restrict__ scales,
             const float* __restrict__ shifta, const float* __restrict__ shiftb,
             float* __restrict__ out)
{
    const int e    = blockIdx.z;
    const int seg0 = g_off[e];
    const int cnt  = g_off[e + 1] - seg0;
    const int tm   = blockIdx.y;
    if (tm * 128 >= cnt) return;
    const int tn = blockIdx.x;

    __shared__ __half As[128 * AS_STRIDE];
    __shared__ __half Bs[32 * BS_STRIDE];
    __shared__ float  Cs[8 * 256];

    const int tid  = threadIdx.x;
    const int wid  = tid >> 5;
    const int lane = tid & 31;
    const int wm   = wid >> 2;
    const int wn   = wid & 3;

    // A loader: g_hid already half — raw 16B copies
    const __half* asrc[2];
    int arow[2], ak8[2];
#pragma unroll
    for (int i = 0; i < 2; i++) {
        int lin = tid + i * 256;
        arow[i] = lin >> 2;
        ak8[i]  = (lin & 3) * 8;
        int gm  = tm * 128 + arow[i];
        int rr  = (gm < cnt) ? gm : 0;
        asrc[i] = g_hid + (size_t)(seg0 + rr) * DHID + ak8[i];
    }
    const float* bsrc[2];
    int bk[2], bn8[2];
    const float* Wbase = W2 + (size_t)e * DHID * DIM + (size_t)tn * 128;
#pragma unroll
    for (int i = 0; i < 2; i++) {
        int lin = tid + i * 256;
        bk[i]  = lin >> 4;
        bn8[i] = (lin & 15) * 8;
        bsrc[i] = Wbase + (size_t)bk[i] * DIM + bn8[i];
    }

    FragC acc[4][2];
#pragma unroll
    for (int i = 0; i < 4; i++)
#pragma unroll
        for (int j = 0; j < 2; j++) wmma::fill_fragment(acc[i][j], 0.0f);

    uint4  pa[2];
    float4 pb[2][2];
#pragma unroll
    for (int i = 0; i < 2; i++) {
        pa[i]    = *(const uint4*)(asrc[i]);
        pb[i][0] = *(const float4*)(bsrc[i]);
        pb[i][1] = *(const float4*)(bsrc[i] + 4);
    }

    const int nstage = DHID / 32;
    for (int kt = 0; kt < nstage; kt++) {
#pragma unroll
        for (int i = 0; i < 2; i++) {
            *(uint4*)&As[arow[i] * AS_STRIDE + ak8[i]] = pa[i];
            *(uint4*)&Bs[bk[i] * BS_STRIDE + bn8[i]]   = f8_to_h8(pb[i][0], pb[i][1]);
        }
        __syncthreads();

        if (kt + 1 < nstage) {
            const int k0 = (kt + 1) * 32;
#pragma unroll
            for (int i = 0; i < 2; i++) {
                pa[i]    = *(const uint4*)(asrc[i] + k0);
                pb[i][0] = *(const float4*)(bsrc[i] + (size_t)k0 * DIM);
                pb[i][1] = *(const float4*)(bsrc[i] + (size_t)k0 * DIM + 4);
            }
        }

#pragma unroll
        for (int kk = 0; kk < 2; kk++) {
            FragA a[4];
            FragB b[2];
#pragma unroll
            for (int fm = 0; fm < 4; fm++)
                wmma::load_matrix_sync(a[fm], &As[(wm * 64 + fm * 16) * AS_STRIDE + kk * 16], AS_STRIDE);
#pragma unroll
            for (int fn = 0; fn < 2; fn++)
                wmma::load_matrix_sync(b[fn], &Bs[(kk * 16) * BS_STRIDE + wn * 32 + fn * 16], BS_STRIDE);
#pragma unroll
            for (int fm = 0; fm < 4; fm++)
#pragma unroll
                for (int fn = 0; fn < 2; fn++)
                    wmma::mma_sync(acc[fm][fn], a[fm], b[fn], acc[fm][fn]);
        }
        __syncthreads();
    }

    const float s_a = sigmoidf_(shifta[0]);
    const float s_b = sigmoidf_(shiftb[0]);
    const float cf  = 0.5f * (s_a + s_b);
    const float cy  = 0.5f * (s_b - s_a);

    float* cbuf = &Cs[wid * 256];
    const float* b2e = b2 + (size_t)e * DIM;
#pragma unroll
    for (int fm = 0; fm < 4; fm++) {
#pragma unroll
        for (int fn = 0; fn < 2; fn++) {
            wmma::store_matrix_sync(cbuf, acc[fm][fn], 16, wmma::mem_row_major);
            __syncwarp();
#pragma unroll
            for (int j = 0; j < 8; j++) {
                int idx = lane + j * 32;
                int r = idx >> 4, c = idx & 15;
                int gm   = tm * 128 + wm * 64 + fm * 16 + r;
                int gcol = tn * 128 + wn * 32 + fn * 16 + c;
                if (gm < cnt) {
                    int orow = g_perm[seg0 + gm];
                    float f = cbuf[idx] + b2e[gcol];
                    f = sigmoidf_(scales[gcol]) * f;
                    out[(size_t)orow * DIM + gcol] = cf * f + cy * y[(size_t)orow * DIM + gcol];
                }
            }
            __syncwarp();
        }
    }
}

// ---------------- launch ----------------
extern "C" void kernel_launch(void* const* d_in, const int* in_sizes, int n_in,
                              void* d_out, int out_size)
{
    const float* t      = (const float*)d_in[0];
    const float* y      = (const float*)d_in[1];
    const float* W1     = (const float*)d_in[2];
    const float* b1     = (const float*)d_in[3];
    const float* W2     = (const float*)d_in[4];
    const float* b2     = (const float*)d_in[5];
    const float* scales = (const float*)d_in[6];
    const float* shifta = (const float*)d_in[7];
    const float* shiftb = (const float*)d_in[8];
    float* out = (float*)d_out;

    k_zero<<<1, 32>>>();
    k_hist<<<(BATCH + 255) / 256, 256>>>(t);
    k_scan<<<1, 1>>>();
    k_scatter<<<(BATCH + 255) / 256, 256>>>(t);

    dim3 g1(DHID / 128, BATCH / 128, NUM_E);
    k_gemm1<<<g1, 256>>>(y, W1, b1);

    dim3 g2(DIM / 128, BATCH / 128, NUM_E);
    k_gemm2<<<g2, 256>>>(y, W2, b2, scales, shifta, shiftb, out);
}

// round 13
// speedup vs baseline: 3.3991x; 1.1301x over previous
#include <cuda_runtime.h>
#include <cuda_fp16.h>
#include <mma.h>
#include <math.h>
#include <stdint.h>

using namespace nvcuda;

#define NUM_E 8
#define BATCH 4096
#define DIM   1024
#define DHID  4096

#define BM 256
#define BN 128
#define BK 32

// --- device scratch (no allocations allowed) ---
__device__ int    g_off[NUM_E + 1];
__device__ int    g_perm[BATCH];
__device__ __half g_hid[(size_t)BATCH * DHID];   // 32 MB, permuted rows, fp16

// ---------------- fused routing: hist + scan + scatter, one block ----------------
__device__ __forceinline__ int expert_of(float t) {
    int e = (int)(t * 8.0f);
    if (e < 0) e = 0;
    if (e > NUM_E - 1) e = NUM_E - 1;
    return e;
}

__global__ void k_route(const float* __restrict__ t) {
    __shared__ int s_cnt[NUM_E], s_cur[NUM_E];
    const int tid = threadIdx.x;
    if (tid < NUM_E) s_cnt[tid] = 0;
    __syncthreads();
    int e_[4];
#pragma unroll
    for (int i = 0; i < 4; i++) {
        e_[i] = expert_of(t[tid + i * 1024]);
        atomicAdd(&s_cnt[e_[i]], 1);
    }
    __syncthreads();
    if (tid == 0) {
        int s = 0;
        for (int e = 0; e < NUM_E; e++) { g_off[e] = s; s_cur[e] = s; s += s_cnt[e]; }
        g_off[NUM_E] = s;
    }
    __syncthreads();
#pragma unroll
    for (int i = 0; i < 4; i++) {
        int p = atomicAdd(&s_cur[e_[i]], 1);
        g_perm[p] = tid + i * 1024;
    }
}

__device__ __forceinline__ float sigmoidf_(float x) { return 1.0f / (1.0f + expf(-x)); }

__device__ __forceinline__ uint4 f8_to_h8(float4 a, float4 b) {
    __half2 h0 = __floats2half2_rn(a.x, a.y);
    __half2 h1 = __floats2half2_rn(a.z, a.w);
    __half2 h2 = __floats2half2_rn(b.x, b.y);
    __half2 h3 = __floats2half2_rn(b.z, b.w);
    uint4 r;
    r.x = *(uint32_t*)&h0; r.y = *(uint32_t*)&h1;
    r.z = *(uint32_t*)&h2; r.w = *(uint32_t*)&h3;
    return r;
}

// ---------------- fp16 WMMA tiles: 256x128x32, 8 warps (4m x 2n), warp = 64x64 ----------------
#define AS_STRIDE 40     // halves (80B rows, 16B-aligned)
#define BS_STRIDE 136    // halves (272B rows, 16B-aligned)

typedef wmma::fragment<wmma::matrix_a, 16, 16, 16, __half, wmma::row_major> FragA;
typedef wmma::fragment<wmma::matrix_b, 16, 16, 16, __half, wmma::row_major> FragB;
typedef wmma::fragment<wmma::accumulator, 16, 16, 16, float> FragC;

// GEMM1: g_hid[seg0+m][n] = half( tanh( y[perm[seg0+m]] . W1[e][:,n] + b1[e][n] ) )
__global__ __launch_bounds__(256, 1)
void k_gemm1(const float* __restrict__ y, const float* __restrict__ W1,
             const float* __restrict__ b1)
{
    const int e    = blockIdx.z;
    const int seg0 = g_off[e];
    const int cnt  = g_off[e + 1] - seg0;
    const int tm   = blockIdx.y;
    if (tm * BM >= cnt) return;
    const int tn = blockIdx.x;

    __shared__ __half As[BM * AS_STRIDE];   // 20 KB
    __shared__ __half Bs[BK * BS_STRIDE];   // 8.5 KB
    __shared__ float  Cs[8 * 256];          // 8 KB

    const int tid  = threadIdx.x;
    const int wid  = tid >> 5;
    const int lane = tid & 31;
    const int wm   = wid >> 1;   // 0..3
    const int wn   = wid & 1;    // 0..1

    // A loader: 4 slots/thread; slot = 8 halves along k. 256 rows x 4 slots/row.
    const float* asrc[4];
    int arow[4], ak8[4];
#pragma unroll
    for (int i = 0; i < 4; i++) {
        int lin = tid + i * 256;           // 0..1023
        arow[i] = lin >> 2;
        ak8[i]  = (lin & 3) * 8;
        int gm  = tm * BM + arow[i];
        int sr  = (gm < cnt) ? g_perm[seg0 + gm] : g_perm[seg0];
        asrc[i] = y + (size_t)sr * DIM + ak8[i];
    }
    // B loader: 2 slots/thread over BK rows x 16 slots (8 halves along n)
    const float* bsrc[2];
    int bk[2], bn8[2];
    const float* Wbase = W1 + (size_t)e * DIM * DHID + (size_t)tn * BN;
#pragma unroll
    for (int i = 0; i < 2; i++) {
        int lin = tid + i * 256;           // 0..511
        bk[i]  = lin >> 4;
        bn8[i] = (lin & 15) * 8;
        bsrc[i] = Wbase + (size_t)bk[i] * DHID + bn8[i];
    }

    FragC acc[4][4];
#pragma unroll
    for (int i = 0; i < 4; i++)
#pragma unroll
        for (int j = 0; j < 4; j++) wmma::fill_fragment(acc[i][j], 0.0f);

    // prefetch stage 0
    float4 pa[4][2], pb[2][2];
#pragma unroll
    for (int i = 0; i < 4; i++) {
        pa[i][0] = *(const float4*)(asrc[i]);
        pa[i][1] = *(const float4*)(asrc[i] + 4);
    }
#pragma unroll
    for (int i = 0; i < 2; i++) {
        pb[i][0] = *(const float4*)(bsrc[i]);
        pb[i][1] = *(const float4*)(bsrc[i] + 4);
    }

    const int nstage = DIM / BK;   // 32
    for (int kt = 0; kt < nstage; kt++) {
#pragma unroll
        for (int i = 0; i < 4; i++)
            *(uint4*)&As[arow[i] * AS_STRIDE + ak8[i]] = f8_to_h8(pa[i][0], pa[i][1]);
#pragma unroll
        for (int i = 0; i < 2; i++)
            *(uint4*)&Bs[bk[i] * BS_STRIDE + bn8[i]] = f8_to_h8(pb[i][0], pb[i][1]);
        __syncthreads();

        if (kt + 1 < nstage) {
            const int k0 = (kt + 1) * BK;
#pragma unroll
            for (int i = 0; i < 4; i++) {
                pa[i][0] = *(const float4*)(asrc[i] + k0);
                pa[i][1] = *(const float4*)(asrc[i] + k0 + 4);
            }
#pragma unroll
            for (int i = 0; i < 2; i++) {
                pb[i][0] = *(const float4*)(bsrc[i] + (size_t)k0 * DHID);
                pb[i][1] = *(const float4*)(bsrc[i] + (size_t)k0 * DHID + 4);
            }
        }

#pragma unroll
        for (int kk = 0; kk < 2; kk++) {
            FragA a[4];
            FragB b[4];
#pragma unroll
            for (int fm = 0; fm < 4; fm++)
                wmma::load_matrix_sync(a[fm], &As[(wm * 64 + fm * 16) * AS_STRIDE + kk * 16], AS_STRIDE);
#pragma unroll
            for (int fn = 0; fn < 4; fn++)
                wmma::load_matrix_sync(b[fn], &Bs[(kk * 16) * BS_STRIDE + wn * 64 + fn * 16], BS_STRIDE);
#pragma unroll
            for (int fm = 0; fm < 4; fm++)
#pragma unroll
                for (int fn = 0; fn < 4; fn++)
                    wmma::mma_sync(acc[fm][fn], a[fm], b[fn], acc[fm][fn]);
        }
        __syncthreads();
    }

    // epilogue: tanh(acc + b1) -> g_hid (half, permuted rows)
    float* cbuf = &Cs[wid * 256];
    const float* b1e = b1 + (size_t)e * DHID;
#pragma unroll
    for (int fm = 0; fm < 4; fm++) {
#pragma unroll
        for (int fn = 0; fn < 4; fn++) {
            wmma::store_matrix_sync(cbuf, acc[fm][fn], 16, wmma::mem_row_major);
            __syncwarp();
#pragma unroll
            for (int j = 0; j < 8; j++) {
                int idx = lane + j * 32;
                int r = idx >> 4, c = idx & 15;
                int gm   = tm * BM + wm * 64 + fm * 16 + r;
                int gcol = tn * BN + wn * 64 + fn * 16 + c;
                if (gm < cnt)
                    g_hid[(size_t)(seg0 + gm) * DHID + gcol] =
                        __float2half_rn(tanhf(cbuf[idx] + b1e[gcol]));
            }
            __syncwarp();
        }
    }
}

// GEMM2 + epilogue: out[perm[m]] = cf*sig(scales)*(hid.W2 + b2) + cy*y[perm[m]]
__global__ __launch_bounds__(256, 1)
void k_gemm2(const float* __restrict__ y, const float* __restrict__ W2,
             const float* __restrict__ b2, const float* __restrict__ scales,
             const float* __restrict__ shifta, const float* __restrict__ shiftb,
             float* __restrict__ out)
{
    const int e    = blockIdx.z;
    const int seg0 = g_off[e];
    const int cnt  = g_off[e + 1] - seg0;
    const int tm   = blockIdx.y;
    if (tm * BM >= cnt) return;
    const int tn = blockIdx.x;

    __shared__ __half As[BM * AS_STRIDE];
    __shared__ __half Bs[BK * BS_STRIDE];
    __shared__ float  Cs[8 * 256];

    const int tid  = threadIdx.x;
    const int wid  = tid >> 5;
    const int lane = tid & 31;
    const int wm   = wid >> 1;
    const int wn   = wid & 1;

    // A loader: g_hid already half — raw 16B copies, 4 slots/thread
    const __half* asrc[4];
    int arow[4], ak8[4];
#pragma unroll
    for (int i = 0; i < 4; i++) {
        int lin = tid + i * 256;
        arow[i] = lin >> 2;
        ak8[i]  = (lin & 3) * 8;
        int gm  = tm * BM + arow[i];
        int rr  = (gm < cnt) ? gm : 0;
        asrc[i] = g_hid + (size_t)(seg0 + rr) * DHID + ak8[i];
    }
    const float* bsrc[2];
    int bk[2], bn8[2];
    const float* Wbase = W2 + (size_t)e * DHID * DIM + (size_t)tn * BN;
#pragma unroll
    for (int i = 0; i < 2; i++) {
        int lin = tid + i * 256;
        bk[i]  = lin >> 4;
        bn8[i] = (lin & 15) * 8;
        bsrc[i] = Wbase + (size_t)bk[i] * DIM + bn8[i];
    }

    FragC acc[4][4];
#pragma unroll
    for (int i = 0; i < 4; i++)
#pragma unroll
        for (int j = 0; j < 4; j++) wmma::fill_fragment(acc[i][j], 0.0f);

    uint4  pa[4];
    float4 pb[2][2];
#pragma unroll
    for (int i = 0; i < 4; i++) pa[i] = *(const uint4*)(asrc[i]);
#pragma unroll
    for (int i = 0; i < 2; i++) {
        pb[i][0] = *(const float4*)(bsrc[i]);
        pb[i][1] = *(const float4*)(bsrc[i] + 4);
    }

    const int nstage = DHID / BK;  // 128
    for (int kt = 0; kt < nstage; kt++) {
#pragma unroll
        for (int i = 0; i < 4; i++)
            *(uint4*)&As[arow[i] * AS_STRIDE + ak8[i]] = pa[i];
#pragma unroll
        for (int i = 0; i < 2; i++)
            *(uint4*)&Bs[bk[i] * BS_STRIDE + bn8[i]] = f8_to_h8(pb[i][0], pb[i][1]);
        __syncthreads();

        if (kt + 1 < nstage) {
            const int k0 = (kt + 1) * BK;
#pragma unroll
            for (int i = 0; i < 4; i++) pa[i] = *(const uint4*)(asrc[i] + k0);
#pragma unroll
            for (int i = 0; i < 2; i++) {
                pb[i][0] = *(const float4*)(bsrc[i] + (size_t)k0 * DIM);
                pb[i][1] = *(const float4*)(bsrc[i] + (size_t)k0 * DIM + 4);
            }
        }

#pragma unroll
        for (int kk = 0; kk < 2; kk++) {
            FragA a[4];
            FragB b[4];
#pragma unroll
            for (int fm = 0; fm < 4; fm++)
                wmma::load_matrix_sync(a[fm], &As[(wm * 64 + fm * 16) * AS_STRIDE + kk * 16], AS_STRIDE);
#pragma unroll
            for (int fn = 0; fn < 4; fn++)
                wmma::load_matrix_sync(b[fn], &Bs[(kk * 16) * BS_STRIDE + wn * 64 + fn * 16], BS_STRIDE);
#pragma unroll
            for (int fm = 0; fm < 4; fm++)
#pragma unroll
                for (int fn = 0; fn < 4; fn++)
                    wmma::mma_sync(acc[fm][fn], a[fm], b[fn], acc[fm][fn]);
        }
        __syncthreads();
    }

    const float s_a = sigmoidf_(shifta[0]);
    const float s_b = sigmoidf_(shiftb[0]);
    const float cf  = 0.5f * (s_a + s_b);
    const float cy  = 0.5f * (s_b - s_a);

    float* cbuf = &Cs[wid * 256];
    const float* b2e = b2 + (size_t)e * DIM;
#pragma unroll
    for (int fm = 0; fm < 4; fm++) {
#pragma unroll
        for (int fn = 0; fn < 4; fn++) {
            wmma::store_matrix_sync(cbuf, acc[fm][fn], 16, wmma::mem_row_major);
            __syncwarp();
#pragma unroll
            for (int j = 0; j < 8; j++) {
                int idx = lane + j * 32;
                int r = idx >> 4, c = idx & 15;
                int gm   = tm * BM + wm * 64 + fm * 16 + r;
                int gcol = tn * BN + wn * 64 + fn * 16 + c;
                if (gm < cnt) {
                    int orow = g_perm[seg0 + gm];
                    float f = cbuf[idx] + b2e[gcol];
                    f = sigmoidf_(scales[gcol]) * f;
                    out[(size_t)orow * DIM + gcol] = cf * f + cy * y[(size_t)orow * DIM + gcol];
                }
            }
            __syncwarp();
        }
    }
}

// ---------------- launch ----------------
extern "C" void kernel_launch(void* const* d_in, const int* in_sizes, int n_in,
                              void* d_out, int out_size)
{
    const float* t      = (const float*)d_in[0];
    const float* y      = (const float*)d_in[1];
    const float* W1     = (const float*)d_in[2];
    const float* b1     = (const float*)d_in[3];
    const float* W2     = (const float*)d_in[4];
    const float* b2     = (const float*)d_in[5];
    const float* scales = (const float*)d_in[6];
    const float* shifta = (const float*)d_in[7];
    const float* shiftb = (const float*)d_in[8];
    float* out = (float*)d_out;

    k_route<<<1, 1024>>>(t);

    dim3 g1(DHID / BN, (BATCH + BM - 1) / BM, NUM_E);
    k_gemm1<<<g1, 256>>>(y, W1, b1);

    dim3 g2(DIM / BN, (BATCH + BM - 1) / BM, NUM_E);
    k_gemm2<<<g2, 256>>>(y, W2, b2, scales, shifta, shiftb, out);
}